// round 17
// baseline (speedup 1.0000x reference)
#include <cuda_runtime.h>
#include <math.h>
#include <stdint.h>

#define Bsz 512
#define Fsz 128
#define Dsz 1024
#define MN (Bsz * Dsz)
#define TSPLIT 4
#define APW 512                 // pair-words (bf16x2) per row
#define ACT_PL (Bsz * APW)      // activation plane words
#define W_PL (Dsz * APW)        // weight plane words

// ---------------- scratch (no allocs -> __device__ globals) ------------------
__device__ float g_qp[MN];
__device__ float g_cb[Bsz];
__device__ float g_part[(size_t)TSPLIT * MN];
__device__ uint32_t g_tlnP[2 * ACT_PL];
__device__ uint32_t g_qP[2 * ACT_PL];
__device__ uint32_t g_sP[2 * ACT_PL];
__device__ uint32_t g_attnP[2 * ACT_PL];
__device__ uint32_t g_alnP[2 * ACT_PL];
__device__ uint32_t g_wqP[2 * W_PL];
__device__ uint32_t g_wkP[2 * W_PL];
__device__ uint32_t g_wvP[2 * W_PL];
__device__ uint32_t g_woP[2 * W_PL];
__device__ uint32_t g_wlP[2 * W_PL];

// ---------------- helpers ----------------------------------------------------
__device__ __forceinline__ void mma16(float* c, const uint32_t* a, const uint32_t* b) {
    asm volatile(
        "mma.sync.aligned.m16n8k16.row.col.f32.bf16.bf16.f32 "
        "{%0,%1,%2,%3}, {%4,%5,%6,%7}, {%8,%9}, {%0,%1,%2,%3};"
        : "+f"(c[0]), "+f"(c[1]), "+f"(c[2]), "+f"(c[3])
        : "r"(a[0]), "r"(a[1]), "r"(a[2]), "r"(a[3]), "r"(b[0]), "r"(b[1]));
}
__device__ __forceinline__ void ldsm4(uint32_t& r0, uint32_t& r1, uint32_t& r2,
                                      uint32_t& r3, uint32_t a) {
    asm volatile("ldmatrix.sync.aligned.m8n8.x4.shared.b16 {%0,%1,%2,%3}, [%4];"
                 : "=r"(r0), "=r"(r1), "=r"(r2), "=r"(r3) : "r"(a));
}
// split float4 (4 consecutive k) into bf16x2 hi/lo pair words
__device__ __forceinline__ void cvt_planes(float4 v, uint32_t& h0, uint32_t& h1,
                                           uint32_t& l0, uint32_t& l1) {
    const uint32_t bx = __float_as_uint(v.x), by = __float_as_uint(v.y);
    const uint32_t bz = __float_as_uint(v.z), bw = __float_as_uint(v.w);
    h0 = (by & 0xFFFF0000u) | (bx >> 16);
    h1 = (bw & 0xFFFF0000u) | (bz >> 16);
    const float lx = v.x - __uint_as_float(bx & 0xFFFF0000u);
    const float ly = v.y - __uint_as_float(by & 0xFFFF0000u);
    const float lz = v.z - __uint_as_float(bz & 0xFFFF0000u);
    const float lw = v.w - __uint_as_float(bw & 0xFFFF0000u);
    asm("cvt.rn.bf16x2.f32 %0, %1, %2;" : "=r"(l0) : "f"(ly), "f"(lx));
    asm("cvt.rn.bf16x2.f32 %0, %1, %2;" : "=r"(l1) : "f"(lw), "f"(lz));
}

// ---------------- weight convert (no transpose) ------------------------------
__global__ __launch_bounds__(256) void cvt_w(const float* __restrict__ W,
                                             uint32_t* __restrict__ hi,
                                             uint32_t* __restrict__ lo) {
    const int idx = blockIdx.x * 256 + threadIdx.x;  // float4 index
    float4 v = ((const float4*)W)[idx];
    uint32_t h0, h1, l0, l1;
    cvt_planes(v, h0, h1, l0, l1);
    ((uint2*)hi)[idx] = make_uint2(h0, h1);
    ((uint2*)lo)[idx] = make_uint2(l0, l1);
}

// ---------------- weight transpose + convert (for k_w) -----------------------
__global__ __launch_bounds__(256) void cvt_wT(const float* __restrict__ W,
                                              uint32_t* __restrict__ hi,
                                              uint32_t* __restrict__ lo) {
    __shared__ float t[32][33];
    const int bx = blockIdx.x, by = blockIdx.y, tid = threadIdx.x;
    const int tx = tid & 31, ty = tid >> 5;  // 8 rows per pass
#pragma unroll
    for (int j = 0; j < 32; j += 8)
        t[ty + j][tx] = W[(size_t)(by * 32 + ty + j) * Dsz + bx * 32 + tx];
    __syncthreads();
#pragma unroll
    for (int w2 = 0; w2 < 2; ++w2) {
        const int item = tid + 256 * w2;
        const int rr = item >> 4, p = item & 15;
        const float a = t[2 * p][rr], b = t[2 * p + 1][rr];
        const uint32_t ba = __float_as_uint(a), bb2 = __float_as_uint(b);
        const uint32_t h = (bb2 & 0xFFFF0000u) | (ba >> 16);
        const float la = a - __uint_as_float(ba & 0xFFFF0000u);
        const float lb = b - __uint_as_float(bb2 & 0xFFFF0000u);
        uint32_t l;
        asm("cvt.rn.bf16x2.f32 %0, %1, %2;" : "=r"(l) : "f"(lb), "f"(la));
        const size_t o = (size_t)(bx * 32 + rr) * APW + by * 16 + p;
        hi[o] = h; lo[o] = l;
    }
}

// ---------------- LN1(text) -> tln planes ------------------------------------
__global__ __launch_bounds__(256) void ln_rows_p(const float* __restrict__ X,
                                                 const float* __restrict__ gam,
                                                 const float* __restrict__ bet,
                                                 uint32_t* __restrict__ hi,
                                                 uint32_t* __restrict__ lo) {
    __shared__ float red[2][8];
    const int row = blockIdx.x, tid = threadIdx.x;
    const int lane = tid & 31, w = tid >> 5;
    float4 x = *(const float4*)(X + (size_t)row * Dsz + tid * 4);
    float ps = x.x + x.y + x.z + x.w;
    float pq = x.x * x.x + x.y * x.y + x.z * x.z + x.w * x.w;
#pragma unroll
    for (int o = 16; o; o >>= 1) {
        ps += __shfl_xor_sync(0xffffffffu, ps, o);
        pq += __shfl_xor_sync(0xffffffffu, pq, o);
    }
    if (lane == 0) { red[0][w] = ps; red[1][w] = pq; }
    __syncthreads();
    float S = 0.f, Q = 0.f;
#pragma unroll
    for (int i = 0; i < 8; ++i) { S += red[0][i]; Q += red[1][i]; }
    const float mu = S * (1.0f / Dsz);
    const float rstd = rsqrtf(Q * (1.0f / Dsz) - mu * mu + 1e-5f);
    float4 g = *(const float4*)(gam + tid * 4);
    float4 b = *(const float4*)(bet + tid * 4);
    float4 o;
    o.x = (x.x - mu) * rstd * g.x + b.x;
    o.y = (x.y - mu) * rstd * g.y + b.y;
    o.z = (x.z - mu) * rstd * g.z + b.z;
    o.w = (x.w - mu) * rstd * g.w + b.w;
    uint32_t h0, h1, l0, l1;
    cvt_planes(o, h0, h1, l0, l1);
    *(uint2*)(hi + (size_t)row * APW + tid * 2) = make_uint2(h0, h1);
    *(uint2*)(lo + (size_t)row * APW + tid * 2) = make_uint2(l0, l1);
}

// ---------------- mma.sync bf16-split GEMM on pre-converted planes ----------
// C[m,n] = sum_k A[m,k]*W[n,k]; 128x128 tile, BK=32 (16 pair-words), split-K=4.
#define NP 20
#define AH(s) ((s) * 10240 + 0)
#define AL(s) ((s) * 10240 + 2560)
#define BHs(s) ((s) * 10240 + 5120)
#define BLs(s) ((s) * 10240 + 7680)
#define GM_SMEM (2 * 10240 * 4)  // 81920 B

__global__ __launch_bounds__(256) void gemm_p(const uint32_t* __restrict__ Ah_,
                                              const uint32_t* __restrict__ Al_,
                                              const uint32_t* __restrict__ Wh_,
                                              const uint32_t* __restrict__ Wl_,
                                              float* __restrict__ P) {
    extern __shared__ uint32_t sm[];
    uint32_t sb;
    asm("{ .reg .u64 t; cvta.to.shared.u64 t, %1; cvt.u32.u64 %0, t; }"
        : "=r"(sb) : "l"(sm));
    const int tid = threadIdx.x, lane = tid & 31, wid = tid >> 5;
    const int bm = blockIdx.x, bn = blockIdx.y, ks = blockIdx.z;
    const int kp0 = ks * 128;  // pair-word base for this split (256 k / 2)
    const int g = lane >> 2, t4 = lane & 3;
    const int wm = (wid & 1) * 64, wn = (wid >> 1) * 32;
    const int rsel = lane & 15, csel = (lane >> 4) * 4;

    float acc[4][4][4];
#pragma unroll
    for (int mi = 0; mi < 4; ++mi)
#pragma unroll
        for (int ni = 0; ni < 4; ++ni)
#pragma unroll
            for (int r = 0; r < 4; ++r) acc[mi][ni][r] = 0.f;

    uint32_t aoff[4], boff[2];
#pragma unroll
    for (int mi = 0; mi < 4; ++mi) aoff[mi] = ((wm + mi * 16 + rsel) * NP + csel) * 4;
#pragma unroll
    for (int p = 0; p < 2; ++p) boff[p] = ((wn + p * 16 + rsel) * NP + csel) * 4;

    const int fr2 = tid >> 2, fj2 = (tid & 3) * 4;  // row 0..63, pair-quad offset
    uint4 pah[2], pal[2], pbh[2], pbl[2];

    // prefetch iter 0
    {
        const int kp = kp0;
#pragma unroll
        for (int L = 0; L < 2; ++L) {
            const size_t ar = (size_t)(bm * 128 + fr2 + L * 64) * APW + kp + fj2;
            const size_t br = (size_t)(bn * 128 + fr2 + L * 64) * APW + kp + fj2;
            pah[L] = *(const uint4*)(Ah_ + ar);
            pal[L] = *(const uint4*)(Al_ + ar);
            pbh[L] = *(const uint4*)(Wh_ + br);
            pbl[L] = *(const uint4*)(Wl_ + br);
        }
    }
    {
        const int off = fr2 * NP + fj2;
#pragma unroll
        for (int L = 0; L < 2; ++L) {
            *(uint4*)(sm + AH(0) + off + L * 64 * NP) = pah[L];
            *(uint4*)(sm + AL(0) + off + L * 64 * NP) = pal[L];
            *(uint4*)(sm + BHs(0) + off + L * 64 * NP) = pbh[L];
            *(uint4*)(sm + BLs(0) + off + L * 64 * NP) = pbl[L];
        }
    }
    __syncthreads();

    for (int it = 0; it < 8; ++it) {
        const int s = it & 1;
        if (it + 1 < 8) {
            const int kp = kp0 + (it + 1) * 16;
#pragma unroll
            for (int L = 0; L < 2; ++L) {
                const size_t ar = (size_t)(bm * 128 + fr2 + L * 64) * APW + kp + fj2;
                const size_t br = (size_t)(bn * 128 + fr2 + L * 64) * APW + kp + fj2;
                pah[L] = *(const uint4*)(Ah_ + ar);
                pal[L] = *(const uint4*)(Al_ + ar);
                pbh[L] = *(const uint4*)(Wh_ + br);
                pbl[L] = *(const uint4*)(Wl_ + br);
            }
        }
        const uint32_t ah_b = sb + AH(s) * 4, al_b = sb + AL(s) * 4;
        const uint32_t bh_b = sb + BHs(s) * 4, bl_b = sb + BLs(s) * 4;
#pragma unroll
        for (int kq = 0; kq < 2; ++kq) {
            const uint32_t kqb = kq * 32;
            uint32_t ah[4][4], al[4][4], bh[4][2], bl[4][2];
#pragma unroll
            for (int mi = 0; mi < 4; ++mi) {
                ldsm4(ah[mi][0], ah[mi][1], ah[mi][2], ah[mi][3], ah_b + aoff[mi] + kqb);
                ldsm4(al[mi][0], al[mi][1], al[mi][2], al[mi][3], al_b + aoff[mi] + kqb);
            }
#pragma unroll
            for (int p = 0; p < 2; ++p) {
                uint32_t r0, r1, r2, r3;
                ldsm4(r0, r1, r2, r3, bh_b + boff[p] + kqb);
                bh[2 * p][0] = r0; bh[2 * p + 1][0] = r1;
                bh[2 * p][1] = r2; bh[2 * p + 1][1] = r3;
                ldsm4(r0, r1, r2, r3, bl_b + boff[p] + kqb);
                bl[2 * p][0] = r0; bl[2 * p + 1][0] = r1;
                bl[2 * p][1] = r2; bl[2 * p + 1][1] = r3;
            }
#pragma unroll
            for (int mi = 0; mi < 4; ++mi)
#pragma unroll
                for (int ni = 0; ni < 4; ++ni) {
                    mma16(acc[mi][ni], ah[mi], bh[ni]);
                    mma16(acc[mi][ni], al[mi], bh[ni]);
                    mma16(acc[mi][ni], ah[mi], bl[ni]);
                }
        }
        if (it + 1 < 8) {
            const int ns = (it + 1) & 1;
            const int off = fr2 * NP + fj2;
#pragma unroll
            for (int L = 0; L < 2; ++L) {
                *(uint4*)(sm + AH(ns) + off + L * 64 * NP) = pah[L];
                *(uint4*)(sm + AL(ns) + off + L * 64 * NP) = pal[L];
                *(uint4*)(sm + BHs(ns) + off + L * 64 * NP) = pbh[L];
                *(uint4*)(sm + BLs(ns) + off + L * 64 * NP) = pbl[L];
            }
        }
        __syncthreads();
    }

    float* Pp = P + (size_t)ks * MN;
#pragma unroll
    for (int mi = 0; mi < 4; ++mi) {
        const int m0 = bm * 128 + wm + mi * 16 + g;
#pragma unroll
        for (int ni = 0; ni < 4; ++ni) {
            const int n = bn * 128 + wn + ni * 8 + 2 * t4;
            *(float2*)(Pp + (size_t)m0 * Dsz + n) =
                make_float2(acc[mi][ni][0], acc[mi][ni][1]);
            *(float2*)(Pp + (size_t)(m0 + 8) * Dsz + n) =
                make_float2(acc[mi][ni][2], acc[mi][ni][3]);
        }
    }
}

// ---------------- combine -> fp32 (for qp), 8 loads upfront ------------------
__global__ __launch_bounds__(256) void combine_f(const float* __restrict__ P,
                                                 float* __restrict__ out) {
    const int i0 = blockIdx.x * 512 + threadIdx.x;
    float4 v[8];
#pragma unroll
    for (int h = 0; h < 2; ++h)
#pragma unroll
        for (int sl = 0; sl < TSPLIT; ++sl)
            v[h * 4 + sl] = ((const float4*)(P + (size_t)sl * MN))[i0 + h * 256];
#pragma unroll
    for (int h = 0; h < 2; ++h) {
        float4 s = v[h * 4];
#pragma unroll
        for (int sl = 1; sl < TSPLIT; ++sl) {
            s.x += v[h * 4 + sl].x; s.y += v[h * 4 + sl].y;
            s.z += v[h * 4 + sl].z; s.w += v[h * 4 + sl].w;
        }
        ((float4*)out)[i0 + h * 256] = s;
    }
}

// ---------------- combine + bias -> planes (for attn input) ------------------
__global__ __launch_bounds__(256) void combine_p(const float* __restrict__ P,
                                                 const float* __restrict__ bias,
                                                 uint32_t* __restrict__ hi,
                                                 uint32_t* __restrict__ lo) {
    const int i0 = blockIdx.x * 512 + threadIdx.x;
    float4 v[8];
#pragma unroll
    for (int h = 0; h < 2; ++h)
#pragma unroll
        for (int sl = 0; sl < TSPLIT; ++sl)
            v[h * 4 + sl] = ((const float4*)(P + (size_t)sl * MN))[i0 + h * 256];
#pragma unroll
    for (int h = 0; h < 2; ++h) {
        const int idx = i0 + h * 256;
        float4 bv = *(const float4*)(bias + ((idx * 4) & (Dsz - 1)));
        float4 s = v[h * 4];
#pragma unroll
        for (int sl = 1; sl < TSPLIT; ++sl) {
            s.x += v[h * 4 + sl].x; s.y += v[h * 4 + sl].y;
            s.z += v[h * 4 + sl].z; s.w += v[h * 4 + sl].w;
        }
        s.x += bv.x; s.y += bv.y; s.z += bv.z; s.w += bv.w;
        uint32_t h0, h1, l0, l1;
        cvt_planes(s, h0, h1, l0, l1);
        ((uint2*)hi)[idx] = make_uint2(h0, h1);
        ((uint2*)lo)[idx] = make_uint2(l0, l1);
    }
}

// ---------------- combine q + bias -> q planes; cb[b] = q[b].k_b -------------
__global__ __launch_bounds__(256) void comb_q_cb(const float* __restrict__ P,
                                                 const float* __restrict__ bias,
                                                 const float* __restrict__ kb,
                                                 uint32_t* __restrict__ hi,
                                                 uint32_t* __restrict__ lo,
                                                 float* __restrict__ cb) {
    __shared__ float red[8];
    const int row = blockIdx.x, tid = threadIdx.x;
    const int lane = tid & 31, w = tid >> 5;
    const size_t off = (size_t)row * Dsz + tid * 4;
    float4 s = *(const float4*)(bias + tid * 4);
#pragma unroll
    for (int sl = 0; sl < TSPLIT; ++sl) {
        float4 v = *(const float4*)(P + (size_t)sl * MN + off);
        s.x += v.x; s.y += v.y; s.z += v.z; s.w += v.w;
    }
    uint32_t h0, h1, l0, l1;
    cvt_planes(s, h0, h1, l0, l1);
    *(uint2*)(hi + (size_t)row * APW + tid * 2) = make_uint2(h0, h1);
    *(uint2*)(lo + (size_t)row * APW + tid * 2) = make_uint2(l0, l1);
    float4 c = *(const float4*)(kb + tid * 4);
    float p = s.x * c.x + s.y * c.y + s.z * c.z + s.w * c.w;
#pragma unroll
    for (int o = 16; o; o >>= 1) p += __shfl_xor_sync(0xffffffffu, p, o);
    if (lane == 0) red[w] = p;
    __syncthreads();
    if (tid == 0) {
        float t = 0.f;
#pragma unroll
        for (int i = 0; i < 8; ++i) t += red[i];
        cb[row] = t;
    }
}

// ---------------- combine + bias + LN2 -> aln planes -------------------------
__global__ __launch_bounds__(256) void comb_ln_p(const float* __restrict__ P,
                                                 const float* __restrict__ bias,
                                                 const float* __restrict__ gam,
                                                 const float* __restrict__ bet,
                                                 uint32_t* __restrict__ hi,
                                                 uint32_t* __restrict__ lo) {
    __shared__ float red[2][8];
    const int row = blockIdx.x, tid = threadIdx.x;
    const int lane = tid & 31, w = tid >> 5;
    const size_t off = (size_t)row * Dsz + tid * 4;
    float4 x = *(const float4*)(bias + tid * 4);
#pragma unroll
    for (int sl = 0; sl < TSPLIT; ++sl) {
        float4 v = *(const float4*)(P + (size_t)sl * MN + off);
        x.x += v.x; x.y += v.y; x.z += v.z; x.w += v.w;
    }
    float ps = x.x + x.y + x.z + x.w;
    float pq = x.x * x.x + x.y * x.y + x.z * x.z + x.w * x.w;
#pragma unroll
    for (int o = 16; o; o >>= 1) {
        ps += __shfl_xor_sync(0xffffffffu, ps, o);
        pq += __shfl_xor_sync(0xffffffffu, pq, o);
    }
    if (lane == 0) { red[0][w] = ps; red[1][w] = pq; }
    __syncthreads();
    float S = 0.f, Q = 0.f;
#pragma unroll
    for (int i = 0; i < 8; ++i) { S += red[0][i]; Q += red[1][i]; }
    const float mu = S * (1.0f / Dsz);
    const float rstd = rsqrtf(Q * (1.0f / Dsz) - mu * mu + 1e-5f);
    float4 g = *(const float4*)(gam + tid * 4);
    float4 b = *(const float4*)(bet + tid * 4);
    float4 o;
    o.x = (x.x - mu) * rstd * g.x + b.x;
    o.y = (x.y - mu) * rstd * g.y + b.y;
    o.z = (x.z - mu) * rstd * g.z + b.z;
    o.w = (x.w - mu) * rstd * g.w + b.w;
    uint32_t h0, h1, l0, l1;
    cvt_planes(o, h0, h1, l0, l1);
    *(uint2*)(hi + (size_t)row * APW + tid * 2) = make_uint2(h0, h1);
    *(uint2*)(lo + (size_t)row * APW + tid * 2) = make_uint2(l0, l1);
}

// ---------------- combine + bias + residual(planes) + LN3 -> fp32 out --------
__global__ __launch_bounds__(256) void comb_ln_res(const float* __restrict__ P,
                                                   const float* __restrict__ bias,
                                                   const uint32_t* __restrict__ resH,
                                                   const uint32_t* __restrict__ resL,
                                                   const float* __restrict__ gam,
                                                   const float* __restrict__ bet,
                                                   float* __restrict__ Y) {
    __shared__ float red[2][8];
    const int row = blockIdx.x, tid = threadIdx.x;
    const int lane = tid & 31, w = tid >> 5;
    const size_t off = (size_t)row * Dsz + tid * 4;
    float4 x = *(const float4*)(bias + tid * 4);
#pragma unroll
    for (int sl = 0; sl < TSPLIT; ++sl) {
        float4 v = *(const float4*)(P + (size_t)sl * MN + off);
        x.x += v.x; x.y += v.y; x.z += v.z; x.w += v.w;
    }
    uint2 hh = *(const uint2*)(resH + (size_t)row * APW + tid * 2);
    uint2 ll = *(const uint2*)(resL + (size_t)row * APW + tid * 2);
    x.x += __uint_as_float(hh.x << 16) + __uint_as_float(ll.x << 16);
    x.y += __uint_as_float(hh.x & 0xFFFF0000u) + __uint_as_float(ll.x & 0xFFFF0000u);
    x.z += __uint_as_float(hh.y << 16) + __uint_as_float(ll.y << 16);
    x.w += __uint_as_float(hh.y & 0xFFFF0000u) + __uint_as_float(ll.y & 0xFFFF0000u);
    float ps = x.x + x.y + x.z + x.w;
    float pq = x.x * x.x + x.y * x.y + x.z * x.z + x.w * x.w;
#pragma unroll
    for (int o = 16; o; o >>= 1) {
        ps += __shfl_xor_sync(0xffffffffu, ps, o);
        pq += __shfl_xor_sync(0xffffffffu, pq, o);
    }
    if (lane == 0) { red[0][w] = ps; red[1][w] = pq; }
    __syncthreads();
    float S = 0.f, Q = 0.f;
#pragma unroll
    for (int i = 0; i < 8; ++i) { S += red[0][i]; Q += red[1][i]; }
    const float mu = S * (1.0f / Dsz);
    const float rstd = rsqrtf(Q * (1.0f / Dsz) - mu * mu + 1e-5f);
    float4 g = *(const float4*)(gam + tid * 4);
    float4 b = *(const float4*)(bet + tid * 4);
    float4 o;
    o.x = (x.x - mu) * rstd * g.x + b.x;
    o.y = (x.y - mu) * rstd * g.y + b.y;
    o.z = (x.z - mu) * rstd * g.z + b.z;
    o.w = (x.w - mu) * rstd * g.w + b.w;
    *(float4*)(Y + off) = o;
}

// ---------------- attention: warp-per-frame, zero in-loop barriers -----------
__global__ __launch_bounds__(256) void attn_warp(const float* __restrict__ video,
                                                 const float* __restrict__ qp,
                                                 const float* __restrict__ cbv,
                                                 const float* __restrict__ gam,
                                                 const float* __restrict__ bet,
                                                 uint32_t* __restrict__ outH,
                                                 uint32_t* __restrict__ outL) {
    __shared__ float sv[8][1028];
    __shared__ float sml[8][3];
    const int b = blockIdx.x, tid = threadIdx.x;
    const int lane = tid & 31, w = tid >> 5;
    const float cbb = cbv[b];

    float4 qg[8];
    float Ap = 0.f, Cp = 0.f;
#pragma unroll
    for (int j = 0; j < 8; ++j) {
        const int d = j * 128 + lane * 4;
        float4 qv = *(const float4*)(qp + (size_t)b * Dsz + d);
        float4 gv = *(const float4*)(gam + d);
        float4 bv = *(const float4*)(bet + d);
        qg[j].x = qv.x * gv.x; qg[j].y = qv.y * gv.y;
        qg[j].z = qv.z * gv.z; qg[j].w = qv.w * gv.w;
        Ap += qg[j].x + qg[j].y + qg[j].z + qg[j].w;
        Cp += qv.x * bv.x + qv.y * bv.y + qv.z * bv.z + qv.w * bv.w;
    }
#pragma unroll
    for (int o = 16; o; o >>= 1) {
        Ap += __shfl_xor_sync(0xffffffffu, Ap, o);
        Cp += __shfl_xor_sync(0xffffffffu, Cp, o);
    }

    const float* base = video + (size_t)b * Fsz * Dsz + (size_t)(w * 16) * Dsz;
    float4 xc[8];
#pragma unroll
    for (int j = 0; j < 8; ++j)
        xc[j] = *(const float4*)(base + j * 128 + lane * 4);

    float m = -1e30f, l = 0.f, s1 = 0.f;
    float4 vac[8];
#pragma unroll
    for (int j = 0; j < 8; ++j) vac[j] = make_float4(0.f, 0.f, 0.f, 0.f);

    for (int fi = 0; fi < 16; ++fi) {
        float4 xn[8];
        if (fi + 1 < 16) {
#pragma unroll
            for (int j = 0; j < 8; ++j)
                xn[j] = *(const float4*)(base + (size_t)(fi + 1) * Dsz + j * 128 + lane * 4);
        }
        float s = 0.f, sq = 0.f, dq = 0.f;
#pragma unroll
        for (int j = 0; j < 8; ++j) {
            s += xc[j].x + xc[j].y + xc[j].z + xc[j].w;
            sq += xc[j].x * xc[j].x + xc[j].y * xc[j].y
                + xc[j].z * xc[j].z + xc[j].w * xc[j].w;
            dq += qg[j].x * xc[j].x + qg[j].y * xc[j].y
                + qg[j].z * xc[j].z + qg[j].w * xc[j].w;
        }
#pragma unroll
        for (int o = 16; o; o >>= 1) {
            s  += __shfl_xor_sync(0xffffffffu, s, o);
            sq += __shfl_xor_sync(0xffffffffu, sq, o);
            dq += __shfl_xor_sync(0xffffffffu, dq, o);
        }
        const float mu = s * (1.0f / Dsz);
        const float rstd = rsqrtf(sq * (1.0f / Dsz) - mu * mu + 1e-5f);
        const float logit = ((dq - mu * Ap) * rstd + Cp + cbb) * 0.03125f;
        const float mn = fmaxf(m, logit);
        const float alpha = __expf(m - mn);
        const float p = __expf(logit - mn);
        const float pr = p * rstd;
        l = l * alpha + p;
        s1 = s1 * alpha + pr * mu;
#pragma unroll
        for (int j = 0; j < 8; ++j) {
            vac[j].x = vac[j].x * alpha + pr * xc[j].x;
            vac[j].y = vac[j].y * alpha + pr * xc[j].y;
            vac[j].z = vac[j].z * alpha + pr * xc[j].z;
            vac[j].w = vac[j].w * alpha + pr * xc[j].w;
        }
        m = mn;
#pragma unroll
        for (int j = 0; j < 8; ++j) xc[j] = xn[j];
    }
#pragma unroll
    for (int j = 0; j < 8; ++j)
        *(float4*)(&sv[w][j * 128 + lane * 4]) = vac[j];
    if (lane == 0) { sml[w][0] = m; sml[w][1] = s1; sml[w][2] = l; }
    __syncthreads();

    const int d0 = tid * 4;
    float M = -1e30f;
#pragma unroll
    for (int ww = 0; ww < 8; ++ww) M = fmaxf(M, sml[ww][0]);
    float L = 0.f, S1 = 0.f;
    float4 V = make_float4(0.f, 0.f, 0.f, 0.f);
#pragma unroll
    for (int ww = 0; ww < 8; ++ww) {
        const float wt = __expf(sml[ww][0] - M);
        L += sml[ww][2] * wt;
        S1 += sml[ww][1] * wt;
        float4 v = *(const float4*)(&sv[ww][d0]);
        V.x += v.x * wt; V.y += v.y * wt; V.z += v.z * wt; V.w += v.w * wt;
    }
    const float inv = 1.0f / L;
    float4 g = *(const float4*)(gam + d0);
    float4 bb = *(const float4*)(bet + d0);
    float4 o;
    o.x = (g.x * (V.x - S1)) * inv + bb.x;
    o.y = (g.y * (V.y - S1)) * inv + bb.y;
    o.z = (g.z * (V.z - S1)) * inv + bb.z;
    o.w = (g.w * (V.w - S1)) * inv + bb.w;
    uint32_t h0, h1, l0, l1;
    cvt_planes(o, h0, h1, l0, l1);
    *(uint2*)(outH + (size_t)b * APW + tid * 2) = make_uint2(h0, h1);
    *(uint2*)(outL + (size_t)b * APW + tid * 2) = make_uint2(l0, l1);
}

// ---------------- driver -----------------------------------------------------
extern "C" void kernel_launch(void* const* d_in, const int* in_sizes, int n_in,
                              void* d_out, int out_size) {
    (void)in_sizes; (void)n_in; (void)out_size;
    const float* text  = (const float*)d_in[0];
    const float* video = (const float*)d_in[1];
    const float* q_w   = (const float*)d_in[2];
    const float* k_w   = (const float*)d_in[3];
    const float* v_w   = (const float*)d_in[4];
    const float* out_w = (const float*)d_in[5];
    const float* lin_w = (const float*)d_in[6];
    const float* q_b   = (const float*)d_in[7];
    const float* k_b   = (const float*)d_in[8];
    const float* v_b   = (const float*)d_in[9];
    const float* out_b = (const float*)d_in[10];
    const float* lin_b = (const float*)d_in[11];
    const float* ln1_g = (const float*)d_in[12];
    const float* ln1_b = (const float*)d_in[13];
    const float* ln2_g = (const float*)d_in[14];
    const float* ln2_b = (const float*)d_in[15];
    const float* ln3_g = (const float*)d_in[16];
    const float* ln3_b = (const float*)d_in[17];
    float* out = (float*)d_out;

    float *qp, *cb, *part;
    uint32_t *tlnP, *qP, *sP, *attnP, *alnP, *wqP, *wkP, *wvP, *woP, *wlP;
    cudaGetSymbolAddress((void**)&qp,   g_qp);
    cudaGetSymbolAddress((void**)&cb,   g_cb);
    cudaGetSymbolAddress((void**)&part, g_part);
    cudaGetSymbolAddress((void**)&tlnP, g_tlnP);
    cudaGetSymbolAddress((void**)&qP,   g_qP);
    cudaGetSymbolAddress((void**)&sP,   g_sP);
    cudaGetSymbolAddress((void**)&attnP, g_attnP);
    cudaGetSymbolAddress((void**)&alnP, g_alnP);
    cudaGetSymbolAddress((void**)&wqP,  g_wqP);
    cudaGetSymbolAddress((void**)&wkP,  g_wkP);
    cudaGetSymbolAddress((void**)&wvP,  g_wvP);
    cudaGetSymbolAddress((void**)&woP,  g_woP);
    cudaGetSymbolAddress((void**)&wlP,  g_wlP);

    cudaFuncSetAttribute(gemm_p, cudaFuncAttributeMaxDynamicSharedMemorySize, GM_SMEM);

    const dim3 gg(4, 8, TSPLIT);
    const int wgrid = Dsz * Dsz / 4 / 256;  // 1024

    // 1: t_ln = LN1(text) -> planes
    ln_rows_p<<<Bsz, 256>>>(text, ln1_g, ln1_b, tlnP, tlnP + ACT_PL);
    // 2-5: weight converts (k_w fused transpose)
    cvt_w<<<wgrid, 256>>>(q_w, wqP, wqP + W_PL);
    cvt_wT<<<dim3(32, 32), 256>>>(k_w, wkP, wkP + W_PL);
    cvt_w<<<wgrid, 256>>>(v_w, wvP, wvP + W_PL);
    cvt_w<<<wgrid, 256>>>(out_w, woP, woP + W_PL);
    // 6: q = t_ln @ q_w.T  (profiled launch under ncu -s 5)
    gemm_p<<<gg, 256, GM_SMEM>>>(tlnP, tlnP + ACT_PL, wqP, wqP + W_PL, part);
    comb_q_cb<<<Bsz, 256>>>(part, q_b, k_b, qP, qP + ACT_PL, cb);
    // qp = q @ k_w
    gemm_p<<<gg, 256, GM_SMEM>>>(qP, qP + ACT_PL, wkP, wkP + W_PL, part);
    combine_f<<<MN / 4 / 512, 256>>>(part, qp);
    cvt_w<<<wgrid, 256>>>(lin_w, wlP, wlP + W_PL);
    // attention over LN1(video) -> s planes
    attn_warp<<<Bsz, 256>>>(video, qp, cb, ln1_g, ln1_b, sP, sP + ACT_PL);
    // attn = s @ v_w.T + v_b -> planes
    gemm_p<<<gg, 256, GM_SMEM>>>(sP, sP + ACT_PL, wvP, wvP + W_PL, part);
    combine_p<<<MN / 4 / 512, 256>>>(part, v_b, attnP, attnP + ACT_PL);
    // aln = LN2(attn @ out_w.T + out_b) -> planes
    gemm_p<<<gg, 256, GM_SMEM>>>(attnP, attnP + ACT_PL, woP, woP + W_PL, part);
    comb_ln_p<<<Bsz, 256>>>(part, out_b, ln2_g, ln2_b, alnP, alnP + ACT_PL);
    // out = LN3(aln + aln @ lin_w.T + lin_b)
    gemm_p<<<gg, 256, GM_SMEM>>>(alnP, alnP + ACT_PL, wlP, wlP + W_PL, part);
    comb_ln_res<<<Bsz, 256>>>(part, lin_b, alnP, alnP + ACT_PL, ln3_g, ln3_b, out);
}